// round 9
// baseline (speedup 1.0000x reference)
#include <cuda_runtime.h>

#define THREADS 512
#define BINS 256
#define NBLOCKS (148 * 4)   // 4 blocks/SM x 512 threads = 2048 threads/SM

// Zero-initialized device scratch. The last block re-zeroes it every call, so
// every graph replay sees identical initial state (deterministic).
__device__ unsigned int g_partial[BINS];
__device__ unsigned int g_ticket;

// Histogram layout h[bin][lane]: lane l only touches column l, so every
// warp-ATOMS hits 32 DISTINCT banks. Structurally conflict-free shared
// atomics (proven R7: L1% 63->33, dur 51.7->47.2).
__device__ __forceinline__ void bin_one(float f, unsigned int* hl) {
    // torch.histc: bins over [-4,4], x==4 -> last bin, outside ignored.
    // (f+4)*32 == fmaf(f,32,128) bit-exactly (x32 is an exact binade shift).
    if (fabsf(f) <= 4.0f) {
        int b = __float2int_rd(fmaf(f, 32.0f, 128.0f));
        b = min(b, BINS - 1);
        atomicAdd(&hl[b << 5], 1u);   // hl already offset by lane
    }
}

__device__ __forceinline__ void bin4(float4 v, unsigned int* hl) {
    bin_one(v.x, hl);
    bin_one(v.y, hl);
    bin_one(v.z, hl);
    bin_one(v.w, hl);
}

__global__ __launch_bounds__(THREADS) void histc_kernel(
    const float4* __restrict__ x, float* __restrict__ out, int n4, int dup)
{
    __shared__ unsigned int h[BINS * 32];   // 32 KB: h[b*32 + lane]
    __shared__ bool is_last;

    #pragma unroll
    for (int i = threadIdx.x; i < BINS * 32; i += THREADS)
        h[i] = 0u;
    __syncthreads();

    const int lane = threadIdx.x & 31;
    unsigned int* hl = &h[lane];

    // Block-contiguous chunking: each block owns a contiguous ~443KB span,
    // threads stride by blockDim within it (fully coalesced). Keeps each
    // SM's live 2MB pages small + sequential (TLB reach == working set at
    // 256MB, and MLP=3 < the MLP>=4 full-PTW-overlap threshold).
    const int nchunk = (n4 + gridDim.x - 1) / gridDim.x;
    const int begin = blockIdx.x * nchunk;
    const int end = min(begin + nchunk, n4);
    const int stride = blockDim.x;

    int i = begin + threadIdx.x;

    // Depth-3 software pipeline: 3 x 16B in flight per thread.
    if (i + 2 * stride < end) {
        float4 a = __ldcs(&x[i]);
        float4 b = __ldcs(&x[i + stride]);
        float4 c = __ldcs(&x[i + 2 * stride]);
        i += 3 * stride;
        for (; i + 2 * stride < end; i += 3 * stride) {
            float4 na = __ldcs(&x[i]);
            bin4(a, hl);
            float4 nb = __ldcs(&x[i + stride]);
            bin4(b, hl);
            float4 nc = __ldcs(&x[i + 2 * stride]);
            bin4(c, hl);
            a = na;
            b = nb;
            c = nc;
        }
        bin4(a, hl);
        bin4(b, hl);
        bin4(c, hl);
    }
    for (; i < end; i += stride) {          // 0..2 leftover vectors
        float4 t = __ldcs(&x[i]);
        bin4(t, hl);
    }
    __syncthreads();

    // Reduce 32 lane-columns per bin. Diagonal read (start at own lane) keeps
    // all 32 lanes of a warp on distinct banks every step.
    if (threadIdx.x < BINS) {
        int b = threadIdx.x;
        unsigned int s = 0;
        #pragma unroll
        for (int k = 0; k < 32; k++)
            s += h[(b << 5) + ((k + lane) & 31)];
        if (s)
            atomicAdd(&g_partial[b], s);
    }

    // Last-block-done epilogue: final block writes both output copies and
    // resets scratch. Plain stores overwrite the harness poison.
    __threadfence();
    if (threadIdx.x == 0) {
        unsigned int t = atomicAdd(&g_ticket, 1u);
        is_last = (t == (unsigned int)gridDim.x - 1u);
    }
    __syncthreads();

    if (is_last && threadIdx.x < BINS) {
        int b = threadIdx.x;
        unsigned int v = atomicAdd(&g_partial[b], 0u);  // L2-coherent read
        float fv = (float)v;
        out[b] = fv;
        if (dup)
            out[b + BINS] = fv;
        g_partial[b] = 0u;      // reset for next graph replay
        if (b == 0)
            g_ticket = 0u;
    }
}

extern "C" void kernel_launch(void* const* d_in, const int* in_sizes, int n_in,
                              void* d_out, int out_size)
{
    const float4* x = (const float4*)d_in[0];
    float* out = (float*)d_out;
    int n4 = in_sizes[0] / 4;
    int dup = (out_size >= 2 * BINS) ? 1 : 0;

    histc_kernel<<<NBLOCKS, THREADS>>>(x, out, n4, dup);
}